// round 13
// baseline (speedup 1.0000x reference)
#include <cuda_runtime.h>
#include <cuda_fp16.h>
#include <cstdint>

// ---------------- problem constants ----------------
#define Bb 4
#define Tt 2048
#define Ee 512
#define Hh 8
#define Ll 5
#define Vv 130
#define Dd 512
#define TD (Tt * Dd)
#define TT (Tt * Tt)
#define QKVW 12288   // packed q|k|v row width

// ---------------- device scratch ----------------
__device__ float  g_y[Bb * Tt * Ee];                   // residual stream fp32
__device__ float  g_h[Bb * Tt * Ee];                   // LN output fp32 (residual source)
__device__ __half g_hh[Bb * Tt * Ee];                  // LN output fp16 (GEMM A)
__device__ __half g_qkvh[Bb * Tt * QKVW];              // packed QKV [B*T, 12288]
__device__ __half g_vt[Bb * Hh * Dd * Tt];             // V transposed [B,H,D,T]
__device__ __half g_sh[(long long)Bb * Hh * Tt * Tt];  // scores/probs fp16 [z,T,T]
__device__ float  g_ao[Bb * Hh * Tt * Dd];             // per-head attn out fp32
__device__ __half g_uh[Bb * Tt * 4 * Ee];              // MLP hidden fp16
__device__ __half g_wqkv[Ll * QKVW * Ee];              // packed per-layer q|k|v weights
__device__ __half g_w1[Ll * 4 * Ee * Ee];
__device__ __half g_w2[Ll * 4 * Ee * Ee];

// ---------------- helpers ----------------
__device__ __forceinline__ void cpa16(uint32_t s, const void* g) {
    asm volatile("cp.async.cg.shared.global [%0], [%1], 16;" :: "r"(s), "l"(g));
}

// ---------------- weight pre-conversion (fp32 -> fp16) ----------------
__global__ void cvtwh_kernel(const float* __restrict__ src, __half* __restrict__ dst)
{
    const long long i = ((long long)blockIdx.x * 256 + threadIdx.x) << 2;
    float4 v = *reinterpret_cast<const float4*>(&src[i]);
    __half2 a = __floats2half2_rn(v.x, v.y);
    __half2 b = __floats2half2_rn(v.z, v.w);
    uint2 pk;
    pk.x = *reinterpret_cast<uint32_t*>(&a);
    pk.y = *reinterpret_cast<uint32_t*>(&b);
    *reinterpret_cast<uint2*>(&dst[i]) = pk;
}

// ---------------- fp16 tensor-core GEMM (m16n8k16), 3-stage cp.async + frag dbuf ----------------
// C = A * B^T ; A row-major [M,K] lda halfs; B row-major [N,K] ldb halfs (NT). 256 thr.
constexpr int BKH = 32;                 // halfs per k-tile (64 bytes)
constexpr int ROWB = 80;                // smem bytes per row (64 + 16 pad; conflict-free)
constexpr int A_STAGE_B = 128 * ROWB;   // 10240 B
constexpr int STAGE_B = 2 * A_STAGE_B;  // 20480 B
constexpr int GSMEM_B = 3 * STAGE_B;    // 61440 B

enum { EPI_F32 = 0, EPI_H = 1, EPI_CAUSALH = 2, EPI_HRELU = 3, EPI_BIASRES = 4 };

template <int EPI>
__device__ __forceinline__ void storep(float* __restrict__ Cf, __half* __restrict__ Ch,
                                       const float* __restrict__ bias, const float* __restrict__ Res,
                                       int ldc, int m, int n, float v0, float v1)
{
    if (EPI == EPI_F32) {
        *reinterpret_cast<float2*>(&Cf[(long long)m * ldc + n]) = make_float2(v0, v1);
    } else if (EPI == EPI_H) {
        *reinterpret_cast<__half2*>(&Ch[(long long)m * ldc + n]) = __floats2half2_rn(v0, v1);
    } else if (EPI == EPI_CAUSALH) {
        v0 *= 0.044194173824159216f;
        v1 *= 0.044194173824159216f;
        if (n > m)     v0 = -3.0e4f;   // in fp16 range; exp -> 0
        if (n + 1 > m) v1 = -3.0e4f;
        *reinterpret_cast<__half2*>(&Ch[(long long)m * ldc + n]) = __floats2half2_rn(v0, v1);
    } else if (EPI == EPI_HRELU) {
        v0 = fmaxf(v0 + bias[n], 0.f);
        v1 = fmaxf(v1 + bias[n + 1], 0.f);
        *reinterpret_cast<__half2*>(&Ch[(long long)m * ldc + n]) = __floats2half2_rn(v0, v1);
    } else {  // EPI_BIASRES
        const float2 r = *reinterpret_cast<const float2*>(&Res[(long long)m * ldc + n]);
        *reinterpret_cast<float2*>(&Cf[(long long)m * ldc + n]) =
            make_float2(v0 + bias[n] + r.x, v1 + bias[n + 1] + r.y);
    }
}

template <int EPI, bool CK, bool ZQK>
__global__ __launch_bounds__(256, 2) void gemmh(
    const __half* __restrict__ A, const __half* __restrict__ B, void* __restrict__ Cv,
    int lda, int ldb, int ldc, int K,
    long long sA_, long long sB_, long long sC_,
    const float* __restrict__ bias, const float* __restrict__ Res)
{
    const int bx = blockIdx.x, by = blockIdx.y, bz = blockIdx.z;
    if (EPI == EPI_CAUSALH && bx > by) return;  // causal: skip strictly-upper tiles

    long long offA, offB;
    if (ZQK) {
        const int b_ = bz >> 3, h_ = bz & 7;
        offA = (long long)b_ * Tt * QKVW + h_ * 512;   // Q slice of packed qkv
        offB = offA + 4096;                            // K slice
    } else {
        offA = (long long)bz * sA_;
        offB = (long long)bz * sB_;
    }
    A += offA; B += offB;
    float*  Cf = (float*)Cv + (long long)bz * sC_;
    __half* Ch = (__half*)Cv + (long long)bz * sC_;

    int Keff = K;
    if (CK) { int ke = (by + 1) * 128; Keff = ke < K ? ke : K; }
    const int NT = Keff / BKH;

    extern __shared__ char smem[];

    const int tid = threadIdx.x;
    const int wid = tid >> 5, lane = tid & 31;
    const int g = lane >> 2, tig = lane & 3;
    const int wm = wid & 1, wn = wid >> 1;     // 2x4 warp grid; warp tile 64x32
    const int m0 = by * 128, n0 = bx * 128;
    const int lr = tid >> 2, lc = tid & 3;     // loader: row 0..63(+64), 16B chunk 0..3

    float c[4][4][4];
#pragma unroll
    for (int i = 0; i < 4; i++)
#pragma unroll
        for (int j = 0; j < 4; j++)
#pragma unroll
            for (int q = 0; q < 4; q++) c[i][j][q] = 0.f;

    auto loadTiles = [&](int st, int kt) {
        const int k0 = kt * BKH;
        char* sA = smem + st * STAGE_B;
        char* sB = sA + A_STAGE_B;
#pragma unroll
        for (int r0 = 0; r0 < 128; r0 += 64) {
            const int r = lr + r0;
            cpa16((uint32_t)__cvta_generic_to_shared(sA + r * ROWB + lc * 16),
                  A + (long long)(m0 + r) * lda + k0 + lc * 8);
            cpa16((uint32_t)__cvta_generic_to_shared(sB + r * ROWB + lc * 16),
                  B + (long long)(n0 + r) * ldb + k0 + lc * 8);
        }
    };

    auto loadFragA = [&](uint32_t af[4][4], int st, int kb) {
        const char* sA = smem + st * STAGE_B;
#pragma unroll
        for (int mt = 0; mt < 4; mt++) {
            const char* base = sA + (wm * 64 + mt * 16 + g) * ROWB + kb + tig * 4;
            af[mt][0] = *reinterpret_cast<const uint32_t*>(base);
            af[mt][1] = *reinterpret_cast<const uint32_t*>(base + 8 * ROWB);
            af[mt][2] = *reinterpret_cast<const uint32_t*>(base + 16);
            af[mt][3] = *reinterpret_cast<const uint32_t*>(base + 8 * ROWB + 16);
        }
    };
    auto loadFragB = [&](uint32_t bf[4][2], int st, int kb) {
        const char* sB = smem + st * STAGE_B + A_STAGE_B;
#pragma unroll
        for (int nt = 0; nt < 4; nt++) {
            const char* base = sB + (wn * 32 + nt * 8 + g) * ROWB + kb + tig * 4;
            bf[nt][0] = *reinterpret_cast<const uint32_t*>(base);
            bf[nt][1] = *reinterpret_cast<const uint32_t*>(base + 16);
        }
    };
    auto mma16 = [&](const uint32_t af[4][4], const uint32_t bf[4][2]) {
#pragma unroll
        for (int mt = 0; mt < 4; mt++)
#pragma unroll
            for (int nt = 0; nt < 4; nt++) {
                asm volatile(
                    "mma.sync.aligned.m16n8k16.row.col.f32.f16.f16.f32 "
                    "{%0,%1,%2,%3}, {%4,%5,%6,%7}, {%8,%9}, {%0,%1,%2,%3};"
                    : "+f"(c[mt][nt][0]), "+f"(c[mt][nt][1]),
                      "+f"(c[mt][nt][2]), "+f"(c[mt][nt][3])
                    : "r"(af[mt][0]), "r"(af[mt][1]), "r"(af[mt][2]), "r"(af[mt][3]),
                      "r"(bf[nt][0]), "r"(bf[nt][1]));
            }
    };

    // ---- prologue ----
    loadTiles(0, 0);
    asm volatile("cp.async.commit_group;");
    if (NT > 1) {
        loadTiles(1, 1);
        asm volatile("cp.async.commit_group;");
        asm volatile("cp.async.wait_group 1;");
    } else {
        asm volatile("cp.async.wait_group 0;");
    }
    __syncthreads();

    uint32_t afA[4][4], bfA[4][2], afB[4][4], bfB[4][2];
    loadFragA(afA, 0, 0);
    loadFragB(bfA, 0, 0);

    // ---- main loop ----
    for (int it = 0; it < NT; ++it) {
        const int st = it % 3;
        loadFragA(afB, st, 32);                 // second k-step (bytes 32..63)
        loadFragB(bfB, st, 32);
        if (it + 2 < NT) {
            loadTiles((it + 2) % 3, it + 2);
            asm volatile("cp.async.commit_group;");
        }
        mma16(afA, bfA);
        if (it + 1 < NT) {
            if (it + 2 < NT) asm volatile("cp.async.wait_group 1;");
            else             asm volatile("cp.async.wait_group 0;");
            __syncthreads();
            loadFragA(afA, (it + 1) % 3, 0);
            loadFragB(bfA, (it + 1) % 3, 0);
        }
        mma16(afB, bfB);
    }

    // ---- epilogue ----
#pragma unroll
    for (int mt = 0; mt < 4; mt++) {
        const int mrow = m0 + wm * 64 + mt * 16 + g;
#pragma unroll
        for (int nt = 0; nt < 4; nt++) {
            const int ncol = n0 + wn * 32 + nt * 8 + tig * 2;
            storep<EPI>(Cf, Ch, bias, Res, ldc, mrow,     ncol, c[mt][nt][0], c[mt][nt][1]);
            storep<EPI>(Cf, Ch, bias, Res, ldc, mrow + 8, ncol, c[mt][nt][2], c[mt][nt][3]);
        }
    }
}

// ---------------- V transpose: packed qkv V slice -> [B,H,D,T] ----------------
__global__ void vtrans_kernel(const __half* __restrict__ qkv, __half* __restrict__ vd)
{
    __shared__ __half tile[32][33];
    const int z = blockIdx.z, b_ = z >> 3, h_ = z & 7;
    const int t0 = blockIdx.x << 5, d0 = blockIdx.y << 5;
    const int tx = threadIdx.x, ty = threadIdx.y;  // 32 x 8
#pragma unroll
    for (int i = ty; i < 32; i += 8)
        tile[i][tx] = qkv[(long long)(b_ * Tt + t0 + i) * QKVW + 8192 + h_ * 512 + d0 + tx];
    __syncthreads();
#pragma unroll
    for (int i = ty; i < 32; i += 8)
        vd[((long long)z * 512 + d0 + i) * 2048 + t0 + tx] = tile[tx][i];
}

// ---------------- LayerNorm: fp32 copy + fp16 copy ----------------
__global__ void ln_kernel(const float* __restrict__ x, const float* __restrict__ g,
                          const float* __restrict__ b, float* __restrict__ out,
                          __half* __restrict__ outh)
{
    const int row = blockIdx.x;
    const float* xr = x + (long long)row * Ee;
    const int tid = threadIdx.x;  // 256
    float v0 = xr[tid], v1 = xr[tid + 256];
    float s = v0 + v1, sq = v0 * v0 + v1 * v1;
#pragma unroll
    for (int o = 16; o; o >>= 1) {
        s  += __shfl_xor_sync(0xffffffffu, s,  o);
        sq += __shfl_xor_sync(0xffffffffu, sq, o);
    }
    __shared__ float ss[8], sqq[8];
    const int warp = tid >> 5, lane = tid & 31;
    if (lane == 0) { ss[warp] = s; sqq[warp] = sq; }
    __syncthreads();
    if (tid == 0) {
        float a = 0.f, c2 = 0.f;
#pragma unroll
        for (int i = 0; i < 8; i++) { a += ss[i]; c2 += sqq[i]; }
        ss[0] = a; sqq[0] = c2;
    }
    __syncthreads();
    const float mu  = ss[0] * (1.f / 512.f);
    const float var = sqq[0] * (1.f / 512.f) - mu * mu;
    const float r = rsqrtf(var + 1e-5f);
    const float o0 = (v0 - mu) * r * g[tid]       + b[tid];
    const float o1 = (v1 - mu) * r * g[tid + 256] + b[tid + 256];
    out[(long long)row * Ee + tid]        = o0;
    out[(long long)row * Ee + tid + 256]  = o1;
    outh[(long long)row * Ee + tid]       = __float2half_rn(o0);
    outh[(long long)row * Ee + tid + 256] = __float2half_rn(o1);
}

// ---------------- causal softmax: fp16 in-place, fp32 internal math ----------------
__global__ void softmaxh_kernel(__half* __restrict__ SH)
{
    const long long r = blockIdx.x;
    const int t = (int)(r & (Tt - 1));
    __half* row = SH + (r << 11);
    const int len8 = (((t >> 7) + 1) << 7) >> 3;   // uint4 count (8 halfs each), <=256
    const int tid = threadIdx.x;                   // 256

    float e[8];
    float mx = -1e30f;
    if (tid < len8) {
        uint4 pk = *reinterpret_cast<const uint4*>(&row[tid << 3]);
        const __half2* hp = reinterpret_cast<const __half2*>(&pk);
#pragma unroll
        for (int j = 0; j < 4; j++) {
            float2 f = __half22float2(hp[j]);
            e[2 * j] = f.x; e[2 * j + 1] = f.y;
            mx = fmaxf(mx, fmaxf(f.x, f.y));
        }
    }
    __shared__ float redmax[8], redsum[8];
#pragma unroll
    for (int o = 16; o; o >>= 1) mx = fmaxf(mx, __shfl_xor_sync(0xffffffffu, mx, o));
    const int warp = tid >> 5, lane = tid & 31;
    if (lane == 0) redmax[warp] = mx;
    __syncthreads();
    mx = redmax[0];
#pragma unroll
    for (int w = 1; w < 8; w++) mx = fmaxf(mx, redmax[w]);

    float sum = 0.f;
    if (tid < len8) {
#pragma unroll
        for (int j = 0; j < 8; j++) { e[j] = expf(e[j] - mx); sum += e[j]; }
    }
#pragma unroll
    for (int o = 16; o; o >>= 1) sum += __shfl_xor_sync(0xffffffffu, sum, o);
    if (lane == 0) redsum[warp] = sum;
    __syncthreads();
    sum = 0.f;
#pragma unroll
    for (int w = 0; w < 8; w++) sum += redsum[w];
    const float inv = 1.f / sum;

    if (tid < len8) {
        __half2 o2[4];
#pragma unroll
        for (int j = 0; j < 4; j++)
            o2[j] = __floats2half2_rn(e[2 * j] * inv, e[2 * j + 1] * inv);
        *reinterpret_cast<uint4*>(&row[tid << 3]) = *reinterpret_cast<uint4*>(o2);
    }
}

// ---------------- embedding ----------------
__global__ void embed_kernel(const int* __restrict__ tokens, const float* __restrict__ emb,
                             const float* __restrict__ pos, float* __restrict__ y)
{
    const long long idx = (long long)blockIdx.x * 256 + threadIdx.x;
    const int e = (int)(idx & (Ee - 1));
    const long long m = idx >> 9;
    const int t = (int)(m & (Tt - 1));
    const int tok = tokens[m];
    y[idx] = emb[(long long)tok * Ee + e] + pos[(long long)t * Ee + e];
}

// ---------------- head sum + residual ----------------
__global__ void headsum_kernel(const float* __restrict__ ao, float* __restrict__ y)
{
    const long long i4 = (long long)blockIdx.x * 256 + threadIdx.x;
    const long long idx = i4 << 2;
    const int e = (int)(idx & (Ee - 1));
    const long long m = idx >> 9;
    const int b_ = (int)(m >> 11);
    const int t = (int)(m & (Tt - 1));
    float4 s = *reinterpret_cast<const float4*>(&y[idx]);
    const long long base = ((long long)(b_ * Hh) << 20) + ((long long)t << 9) + e;
#pragma unroll
    for (int h = 0; h < Hh; h++) {
        float4 a = *reinterpret_cast<const float4*>(&ao[base + ((long long)h << 20)]);
        s.x += a.x; s.y += a.y; s.z += a.z; s.w += a.w;
    }
    *reinterpret_cast<float4*>(&y[idx]) = s;
}

// ---------------- logits ----------------
__global__ void logits_kernel(const float* __restrict__ y, const float* __restrict__ Wout,
                              const float* __restrict__ bout, float* __restrict__ out)
{
    const int warp = threadIdx.x >> 5, lane = threadIdx.x & 31;
    const int m = blockIdx.x * 8 + warp;
    const float* yr = y + (long long)m * Ee;
    float yreg[16];
#pragma unroll
    for (int i = 0; i < 16; i++) yreg[i] = yr[lane + i * 32];
    for (int n = 0; n < Vv; n++) {
        const float* w = Wout + (long long)n * Ee;
        float s = 0.f;
#pragma unroll
        for (int i = 0; i < 16; i++) s = fmaf(yreg[i], w[lane + i * 32], s);
#pragma unroll
        for (int o = 16; o; o >>= 1) s += __shfl_xor_sync(0xffffffffu, s, o);
        if (lane == 0) out[(long long)m * Vv + n] = s + bout[n];
    }
}

// ---------------- driver ----------------
extern "C" void kernel_launch(void* const* d_in, const int* in_sizes, int n_in,
                              void* d_out, int out_size)
{
    const int*   tokens = (const int*)  d_in[0];
    const float* emb    = (const float*)d_in[1];
    const float* pos    = (const float*)d_in[2];
    const float* ln1_g  = (const float*)d_in[3];
    const float* ln1_b  = (const float*)d_in[4];
    const float* Wq     = (const float*)d_in[5];
    const float* Wk     = (const float*)d_in[6];
    const float* Wv     = (const float*)d_in[7];
    const float* ln2_g  = (const float*)d_in[8];
    const float* ln2_b  = (const float*)d_in[9];
    const float* W1     = (const float*)d_in[10];
    const float* b1     = (const float*)d_in[11];
    const float* W2     = (const float*)d_in[12];
    const float* b2     = (const float*)d_in[13];
    const float* Wout   = (const float*)d_in[14];
    const float* bout   = (const float*)d_in[15];
    float* out = (float*)d_out;

    float *y, *h, *ao;
    __half *hh, *qkvh, *vt, *sh, *uh, *wqkv, *w1, *w2;
    cudaGetSymbolAddress((void**)&y,    g_y);
    cudaGetSymbolAddress((void**)&h,    g_h);
    cudaGetSymbolAddress((void**)&hh,   g_hh);
    cudaGetSymbolAddress((void**)&qkvh, g_qkvh);
    cudaGetSymbolAddress((void**)&vt,   g_vt);
    cudaGetSymbolAddress((void**)&sh,   g_sh);
    cudaGetSymbolAddress((void**)&ao,   g_ao);
    cudaGetSymbolAddress((void**)&uh,   g_uh);
    cudaGetSymbolAddress((void**)&wqkv, g_wqkv);
    cudaGetSymbolAddress((void**)&w1,   g_w1);
    cudaGetSymbolAddress((void**)&w2,   g_w2);

    cudaFuncSetAttribute(gemmh<EPI_H,      false, false>, cudaFuncAttributeMaxDynamicSharedMemorySize, GSMEM_B);
    cudaFuncSetAttribute(gemmh<EPI_CAUSALH,false, true >, cudaFuncAttributeMaxDynamicSharedMemorySize, GSMEM_B);
    cudaFuncSetAttribute(gemmh<EPI_F32,    true,  false>, cudaFuncAttributeMaxDynamicSharedMemorySize, GSMEM_B);
    cudaFuncSetAttribute(gemmh<EPI_HRELU,  false, false>, cudaFuncAttributeMaxDynamicSharedMemorySize, GSMEM_B);
    cudaFuncSetAttribute(gemmh<EPI_BIASRES,false, false>, cudaFuncAttributeMaxDynamicSharedMemorySize, GSMEM_B);

    const int MBT = Bb * Tt;  // 8192
    const int NMAT = Hh * Dd * Ee;      // 2.10M elements per q/k/v matrix per layer
    const int NMLP = Ll * 4 * Ee * Ee;  // 5.24M

    // pack q|k|v weights per layer into wqkv [L][12288][512], fp16
    for (int l = 0; l < Ll; l++) {
        __half* dst = wqkv + (long long)l * QKVW * Ee;
        cvtwh_kernel<<<NMAT / 1024, 256>>>(Wq + (long long)l * NMAT, dst);
        cvtwh_kernel<<<NMAT / 1024, 256>>>(Wk + (long long)l * NMAT, dst + (long long)4096 * Ee);
        cvtwh_kernel<<<NMAT / 1024, 256>>>(Wv + (long long)l * NMAT, dst + (long long)8192 * Ee);
    }
    cvtwh_kernel<<<NMLP / 1024, 256>>>(W1, w1);
    cvtwh_kernel<<<NMLP / 1024, 256>>>(W2, w2);

    embed_kernel<<<(MBT * Ee) / 256, 256>>>(tokens, emb, pos, y);

    for (int l = 0; l < Ll; l++) {
        ln_kernel<<<MBT, 256>>>(y, ln1_g + l * Ee, ln1_b + l * Ee, h, hh);

        // fused QKV projection: [8192,512] x [12288,512]^T -> qkvh [8192,12288]
        dim3 gqkv(96, 64);
        gemmh<EPI_H, false, false><<<gqkv, 256, GSMEM_B>>>(
            hh, wqkv + (long long)l * QKVW * Ee, qkvh,
            512, 512, QKVW, 512, 0, 0, 0, nullptr, nullptr);

        vtrans_kernel<<<dim3(Tt / 32, Dd / 32, Bb * Hh), dim3(32, 8)>>>(qkvh, vt);

        // S = scale * Q K^T (causal), fp16 out, per head via ZQK offsets
        dim3 gqk(16, 16, 32);
        gemmh<EPI_CAUSALH, false, true><<<gqk, 256, GSMEM_B>>>(
            qkvh, qkvh, sh, QKVW, QKVW, 2048, 512, 0, 0, (long long)TT, nullptr, nullptr);

        softmaxh_kernel<<<Bb * Hh * Tt, 256>>>(sh);

        // AO = P V (NT with transposed V), causal K-bound; fp32 out
        dim3 gav(4, 16, 32);
        gemmh<EPI_F32, true, false><<<gav, 256, GSMEM_B>>>(
            sh, vt, ao, 2048, 2048, 512, 2048,
            (long long)TT, (long long)(1 << 20), (long long)TD, nullptr, nullptr);

        headsum_kernel<<<(MBT * Ee) / 1024, 256>>>(ao, y);

        ln_kernel<<<MBT, 256>>>(y, ln2_g + l * Ee, ln2_b + l * Ee, h, hh);

        // u = relu(h2 W1^T + b1), half out
        dim3 g1(16, 64);
        gemmh<EPI_HRELU, false, false><<<g1, 256, GSMEM_B>>>(
            hh, w1 + (long long)l * 4 * Ee * Ee, uh, 512, 512, 2048, 512,
            0, 0, 0, b1 + l * 4 * Ee, nullptr);

        // y = u W2^T + b2 + h2, fp32 out
        dim3 g2(4, 64);
        gemmh<EPI_BIASRES, false, false><<<g2, 256, GSMEM_B>>>(
            uh, w2 + (long long)l * Ee * 4 * Ee, y, 2048, 2048, 512, 2048,
            0, 0, 0, b2 + l * Ee, h);
    }

    logits_kernel<<<MBT / 8, 256>>>(y, Wout, bout, out);
}

// round 15
// speedup vs baseline: 1.0404x; 1.0404x over previous
#include <cuda_runtime.h>
#include <cuda_fp16.h>
#include <cstdint>

// ---------------- problem constants ----------------
#define Bb 4
#define Tt 2048
#define Ee 512
#define Hh 8
#define Ll 5
#define Vv 130
#define Dd 512
#define TD (Tt * Dd)
#define TT (Tt * Tt)
#define QKVW 12288   // packed q|k|v row width

// ---------------- device scratch ----------------
__device__ float  g_y[Bb * Tt * Ee];                   // residual stream fp32
__device__ float  g_h[Bb * Tt * Ee];                   // LN output fp32 (residual source)
__device__ __half g_hh[Bb * Tt * Ee];                  // LN output fp16 (GEMM A)
__device__ __half g_qkvh[Bb * Tt * QKVW];              // packed QKV [B*T, 12288]
__device__ __half g_vt[Bb * Hh * Dd * Tt];             // V transposed [B,H,D,T]
__device__ __half g_sh[(long long)Bb * Hh * Tt * Tt];  // scores/probs fp16 [z,T,T]
__device__ float  g_ao[Bb * Hh * Tt * Dd];             // per-head attn out fp32
__device__ __half g_uh[Bb * Tt * 4 * Ee];              // MLP hidden fp16
__device__ __half g_wqkv[Ll * QKVW * Ee];              // packed per-layer q|k|v weights
__device__ __half g_w1[Ll * 4 * Ee * Ee];
__device__ __half g_w2[Ll * 4 * Ee * Ee];

// ---------------- helpers ----------------
__device__ __forceinline__ void cpa16(uint32_t s, const void* g) {
    asm volatile("cp.async.cg.shared.global [%0], [%1], 16;" :: "r"(s), "l"(g));
}

// ---------------- weight pre-conversion (fp32 -> fp16) ----------------
__global__ void cvtwh_kernel(const float* __restrict__ src, __half* __restrict__ dst)
{
    const long long i = ((long long)blockIdx.x * 256 + threadIdx.x) << 2;
    float4 v = *reinterpret_cast<const float4*>(&src[i]);
    __half2 a = __floats2half2_rn(v.x, v.y);
    __half2 b = __floats2half2_rn(v.z, v.w);
    uint2 pk;
    pk.x = *reinterpret_cast<uint32_t*>(&a);
    pk.y = *reinterpret_cast<uint32_t*>(&b);
    *reinterpret_cast<uint2*>(&dst[i]) = pk;
}

// ---------------- fp16 tensor-core GEMM (m16n8k16), 3-stage cp.async + frag dbuf + LDSM ----------------
// C = A * B^T ; A row-major [M,K] lda halfs; B row-major [N,K] ldb halfs (NT). 256 thr.
constexpr int BKH = 32;                 // halfs per k-tile (64 bytes)
constexpr int ROWB = 80;                // smem bytes per row (64 + 16 pad; conflict-free)
constexpr int A_STAGE_B = 128 * ROWB;   // 10240 B
constexpr int STAGE_B = 2 * A_STAGE_B;  // 20480 B
constexpr int GSMEM_B = 3 * STAGE_B;    // 61440 B

enum { EPI_F32 = 0, EPI_H = 1, EPI_CAUSALH = 2, EPI_HRELU = 3, EPI_BIASRES = 4 };

template <int EPI>
__device__ __forceinline__ void storep(float* __restrict__ Cf, __half* __restrict__ Ch,
                                       const float* __restrict__ bias, const float* __restrict__ Res,
                                       int ldc, int m, int n, float v0, float v1)
{
    if (EPI == EPI_F32) {
        *reinterpret_cast<float2*>(&Cf[(long long)m * ldc + n]) = make_float2(v0, v1);
    } else if (EPI == EPI_H) {
        *reinterpret_cast<__half2*>(&Ch[(long long)m * ldc + n]) = __floats2half2_rn(v0, v1);
    } else if (EPI == EPI_CAUSALH) {
        v0 *= 0.044194173824159216f;
        v1 *= 0.044194173824159216f;
        if (n > m)     v0 = -3.0e4f;   // in fp16 range; exp -> 0
        if (n + 1 > m) v1 = -3.0e4f;
        *reinterpret_cast<__half2*>(&Ch[(long long)m * ldc + n]) = __floats2half2_rn(v0, v1);
    } else if (EPI == EPI_HRELU) {
        v0 = fmaxf(v0 + bias[n], 0.f);
        v1 = fmaxf(v1 + bias[n + 1], 0.f);
        *reinterpret_cast<__half2*>(&Ch[(long long)m * ldc + n]) = __floats2half2_rn(v0, v1);
    } else {  // EPI_BIASRES
        const float2 r = *reinterpret_cast<const float2*>(&Res[(long long)m * ldc + n]);
        *reinterpret_cast<float2*>(&Cf[(long long)m * ldc + n]) =
            make_float2(v0 + bias[n] + r.x, v1 + bias[n + 1] + r.y);
    }
}

template <int EPI, bool CK, bool ZQK>
__global__ __launch_bounds__(256, 2) void gemmh(
    const __half* __restrict__ A, const __half* __restrict__ B, void* __restrict__ Cv,
    int lda, int ldb, int ldc, int K,
    long long sA_, long long sB_, long long sC_,
    const float* __restrict__ bias, const float* __restrict__ Res)
{
    const int bx = blockIdx.x, by = blockIdx.y, bz = blockIdx.z;
    if (EPI == EPI_CAUSALH && bx > by) return;  // causal: skip strictly-upper tiles

    long long offA, offB;
    if (ZQK) {
        const int b_ = bz >> 3, h_ = bz & 7;
        offA = (long long)b_ * Tt * QKVW + h_ * 512;   // Q slice of packed qkv
        offB = offA + 4096;                            // K slice
    } else {
        offA = (long long)bz * sA_;
        offB = (long long)bz * sB_;
    }
    A += offA; B += offB;
    float*  Cf = (float*)Cv + (long long)bz * sC_;
    __half* Ch = (__half*)Cv + (long long)bz * sC_;

    int Keff = K;
    if (CK) { int ke = (by + 1) * 128; Keff = ke < K ? ke : K; }
    const int NT = Keff / BKH;

    extern __shared__ char smem[];
    const uint32_t smem_u = (uint32_t)__cvta_generic_to_shared(smem);

    const int tid = threadIdx.x;
    const int wid = tid >> 5, lane = tid & 31;
    const int g = lane >> 2, tig = lane & 3;
    const int wm = wid & 1, wn = wid >> 1;     // 2x4 warp grid; warp tile 64x32
    const int m0 = by * 128, n0 = bx * 128;
    const int lr = tid >> 2, lc = tid & 3;     // loader: row 0..63(+64), 16B chunk 0..3

    // ldmatrix lane-address components
    const int aRowSel = lane & 15;             // row within 16-row A tile
    const int aByte   = (lane >> 4) << 4;      // 0 or 16 (k halves)
    const int bRowSel = lane & 7;              // row within 8-row B tile
    const int bByte   = ((lane >> 3) & 1) << 4;

    float c[4][4][4];
#pragma unroll
    for (int i = 0; i < 4; i++)
#pragma unroll
        for (int j = 0; j < 4; j++)
#pragma unroll
            for (int q = 0; q < 4; q++) c[i][j][q] = 0.f;

    auto loadTiles = [&](int st, int kt) {
        const int k0 = kt * BKH;
        char* sA = smem + st * STAGE_B;
        char* sB = sA + A_STAGE_B;
#pragma unroll
        for (int r0 = 0; r0 < 128; r0 += 64) {
            const int r = lr + r0;
            cpa16((uint32_t)__cvta_generic_to_shared(sA + r * ROWB + lc * 16),
                  A + (long long)(m0 + r) * lda + k0 + lc * 8);
            cpa16((uint32_t)__cvta_generic_to_shared(sB + r * ROWB + lc * 16),
                  B + (long long)(n0 + r) * ldb + k0 + lc * 8);
        }
    };

    auto loadFragA = [&](uint32_t af[4][4], int st, int kb) {
        const uint32_t sA = smem_u + st * STAGE_B;
#pragma unroll
        for (int mt = 0; mt < 4; mt++) {
            const uint32_t addr = sA + (wm * 64 + mt * 16 + aRowSel) * ROWB + kb + aByte;
            asm volatile("ldmatrix.sync.aligned.m8n8.x4.shared.b16 {%0,%1,%2,%3}, [%4];"
                         : "=r"(af[mt][0]), "=r"(af[mt][1]), "=r"(af[mt][2]), "=r"(af[mt][3])
                         : "r"(addr));
        }
    };
    auto loadFragB = [&](uint32_t bf[4][2], int st, int kb) {
        const uint32_t sB = smem_u + st * STAGE_B + A_STAGE_B;
#pragma unroll
        for (int nt = 0; nt < 4; nt++) {
            const uint32_t addr = sB + (wn * 32 + nt * 8 + bRowSel) * ROWB + kb + bByte;
            asm volatile("ldmatrix.sync.aligned.m8n8.x2.shared.b16 {%0,%1}, [%2];"
                         : "=r"(bf[nt][0]), "=r"(bf[nt][1])
                         : "r"(addr));
        }
    };
    auto mma16 = [&](const uint32_t af[4][4], const uint32_t bf[4][2]) {
#pragma unroll
        for (int mt = 0; mt < 4; mt++)
#pragma unroll
            for (int nt = 0; nt < 4; nt++) {
                asm volatile(
                    "mma.sync.aligned.m16n8k16.row.col.f32.f16.f16.f32 "
                    "{%0,%1,%2,%3}, {%4,%5,%6,%7}, {%8,%9}, {%0,%1,%2,%3};"
                    : "+f"(c[mt][nt][0]), "+f"(c[mt][nt][1]),
                      "+f"(c[mt][nt][2]), "+f"(c[mt][nt][3])
                    : "r"(af[mt][0]), "r"(af[mt][1]), "r"(af[mt][2]), "r"(af[mt][3]),
                      "r"(bf[nt][0]), "r"(bf[nt][1]));
            }
    };

    // ---- prologue ----
    loadTiles(0, 0);
    asm volatile("cp.async.commit_group;");
    if (NT > 1) {
        loadTiles(1, 1);
        asm volatile("cp.async.commit_group;");
        asm volatile("cp.async.wait_group 1;");
    } else {
        asm volatile("cp.async.wait_group 0;");
    }
    __syncthreads();

    uint32_t afA[4][4], bfA[4][2], afB[4][4], bfB[4][2];
    loadFragA(afA, 0, 0);
    loadFragB(bfA, 0, 0);

    // ---- main loop ----
    for (int it = 0; it < NT; ++it) {
        const int st = it % 3;
        loadFragA(afB, st, 32);                 // second k-step (bytes 32..63)
        loadFragB(bfB, st, 32);
        if (it + 2 < NT) {
            loadTiles((it + 2) % 3, it + 2);
            asm volatile("cp.async.commit_group;");
        }
        mma16(afA, bfA);
        if (it + 1 < NT) {
            if (it + 2 < NT) asm volatile("cp.async.wait_group 1;");
            else             asm volatile("cp.async.wait_group 0;");
            __syncthreads();
            loadFragA(afA, (it + 1) % 3, 0);
            loadFragB(bfA, (it + 1) % 3, 0);
        }
        mma16(afB, bfB);
    }

    // ---- epilogue ----
#pragma unroll
    for (int mt = 0; mt < 4; mt++) {
        const int mrow = m0 + wm * 64 + mt * 16 + g;
#pragma unroll
        for (int nt = 0; nt < 4; nt++) {
            const int ncol = n0 + wn * 32 + nt * 8 + tig * 2;
            storep<EPI>(Cf, Ch, bias, Res, ldc, mrow,     ncol, c[mt][nt][0], c[mt][nt][1]);
            storep<EPI>(Cf, Ch, bias, Res, ldc, mrow + 8, ncol, c[mt][nt][2], c[mt][nt][3]);
        }
    }
}

// ---------------- V transpose: packed qkv V slice -> [B,H,D,T] ----------------
__global__ void vtrans_kernel(const __half* __restrict__ qkv, __half* __restrict__ vd)
{
    __shared__ __half tile[32][33];
    const int z = blockIdx.z, b_ = z >> 3, h_ = z & 7;
    const int t0 = blockIdx.x << 5, d0 = blockIdx.y << 5;
    const int tx = threadIdx.x, ty = threadIdx.y;  // 32 x 8
#pragma unroll
    for (int i = ty; i < 32; i += 8)
        tile[i][tx] = qkv[(long long)(b_ * Tt + t0 + i) * QKVW + 8192 + h_ * 512 + d0 + tx];
    __syncthreads();
#pragma unroll
    for (int i = ty; i < 32; i += 8)
        vd[((long long)z * 512 + d0 + i) * 2048 + t0 + tx] = tile[tx][i];
}

// ---------------- LayerNorm: fp32 copy + fp16 copy ----------------
__global__ void ln_kernel(const float* __restrict__ x, const float* __restrict__ g,
                          const float* __restrict__ b, float* __restrict__ out,
                          __half* __restrict__ outh)
{
    const int row = blockIdx.x;
    const float* xr = x + (long long)row * Ee;
    const int tid = threadIdx.x;  // 256
    float v0 = xr[tid], v1 = xr[tid + 256];
    float s = v0 + v1, sq = v0 * v0 + v1 * v1;
#pragma unroll
    for (int o = 16; o; o >>= 1) {
        s  += __shfl_xor_sync(0xffffffffu, s,  o);
        sq += __shfl_xor_sync(0xffffffffu, sq, o);
    }
    __shared__ float ss[8], sqq[8];
    const int warp = tid >> 5, lane = tid & 31;
    if (lane == 0) { ss[warp] = s; sqq[warp] = sq; }
    __syncthreads();
    if (tid == 0) {
        float a = 0.f, c2 = 0.f;
#pragma unroll
        for (int i = 0; i < 8; i++) { a += ss[i]; c2 += sqq[i]; }
        ss[0] = a; sqq[0] = c2;
    }
    __syncthreads();
    const float mu  = ss[0] * (1.f / 512.f);
    const float var = sqq[0] * (1.f / 512.f) - mu * mu;
    const float r = rsqrtf(var + 1e-5f);
    const float o0 = (v0 - mu) * r * g[tid]       + b[tid];
    const float o1 = (v1 - mu) * r * g[tid + 256] + b[tid + 256];
    out[(long long)row * Ee + tid]        = o0;
    out[(long long)row * Ee + tid + 256]  = o1;
    outh[(long long)row * Ee + tid]       = __float2half_rn(o0);
    outh[(long long)row * Ee + tid + 256] = __float2half_rn(o1);
}

// ---------------- causal softmax: fp16 in-place, fp32 internal math ----------------
__global__ void softmaxh_kernel(__half* __restrict__ SH)
{
    const long long r = blockIdx.x;
    const int t = (int)(r & (Tt - 1));
    __half* row = SH + (r << 11);
    const int len8 = (((t >> 7) + 1) << 7) >> 3;   // uint4 count (8 halfs each), <=256
    const int tid = threadIdx.x;                   // 256

    float e[8];
    float mx = -1e30f;
    if (tid < len8) {
        uint4 pk = *reinterpret_cast<const uint4*>(&row[tid << 3]);
        const __half2* hp = reinterpret_cast<const __half2*>(&pk);
#pragma unroll
        for (int j = 0; j < 4; j++) {
            float2 f = __half22float2(hp[j]);
            e[2 * j] = f.x; e[2 * j + 1] = f.y;
            mx = fmaxf(mx, fmaxf(f.x, f.y));
        }
    }
    __shared__ float redmax[8], redsum[8];
#pragma unroll
    for (int o = 16; o; o >>= 1) mx = fmaxf(mx, __shfl_xor_sync(0xffffffffu, mx, o));
    const int warp = tid >> 5, lane = tid & 31;
    if (lane == 0) redmax[warp] = mx;
    __syncthreads();
    mx = redmax[0];
#pragma unroll
    for (int w = 1; w < 8; w++) mx = fmaxf(mx, redmax[w]);

    float sum = 0.f;
    if (tid < len8) {
#pragma unroll
        for (int j = 0; j < 8; j++) { e[j] = expf(e[j] - mx); sum += e[j]; }
    }
#pragma unroll
    for (int o = 16; o; o >>= 1) sum += __shfl_xor_sync(0xffffffffu, sum, o);
    if (lane == 0) redsum[warp] = sum;
    __syncthreads();
    sum = 0.f;
#pragma unroll
    for (int w = 0; w < 8; w++) sum += redsum[w];
    const float inv = 1.f / sum;

    if (tid < len8) {
        __half2 o2[4];
#pragma unroll
        for (int j = 0; j < 4; j++)
            o2[j] = __floats2half2_rn(e[2 * j] * inv, e[2 * j + 1] * inv);
        *reinterpret_cast<uint4*>(&row[tid << 3]) = *reinterpret_cast<uint4*>(o2);
    }
}

// ---------------- embedding ----------------
__global__ void embed_kernel(const int* __restrict__ tokens, const float* __restrict__ emb,
                             const float* __restrict__ pos, float* __restrict__ y)
{
    const long long idx = (long long)blockIdx.x * 256 + threadIdx.x;
    const int e = (int)(idx & (Ee - 1));
    const long long m = idx >> 9;
    const int t = (int)(m & (Tt - 1));
    const int tok = tokens[m];
    y[idx] = emb[(long long)tok * Ee + e] + pos[(long long)t * Ee + e];
}

// ---------------- head sum + residual ----------------
__global__ void headsum_kernel(const float* __restrict__ ao, float* __restrict__ y)
{
    const long long i4 = (long long)blockIdx.x * 256 + threadIdx.x;
    const long long idx = i4 << 2;
    const int e = (int)(idx & (Ee - 1));
    const long long m = idx >> 9;
    const int b_ = (int)(m >> 11);
    const int t = (int)(m & (Tt - 1));
    float4 s = *reinterpret_cast<const float4*>(&y[idx]);
    const long long base = ((long long)(b_ * Hh) << 20) + ((long long)t << 9) + e;
#pragma unroll
    for (int h = 0; h < Hh; h++) {
        float4 a = *reinterpret_cast<const float4*>(&ao[base + ((long long)h << 20)]);
        s.x += a.x; s.y += a.y; s.z += a.z; s.w += a.w;
    }
    *reinterpret_cast<float4*>(&y[idx]) = s;
}

// ---------------- logits ----------------
__global__ void logits_kernel(const float* __restrict__ y, const float* __restrict__ Wout,
                              const float* __restrict__ bout, float* __restrict__ out)
{
    const int warp = threadIdx.x >> 5, lane = threadIdx.x & 31;
    const int m = blockIdx.x * 8 + warp;
    const float* yr = y + (long long)m * Ee;
    float yreg[16];
#pragma unroll
    for (int i = 0; i < 16; i++) yreg[i] = yr[lane + i * 32];
    for (int n = 0; n < Vv; n++) {
        const float* w = Wout + (long long)n * Ee;
        float s = 0.f;
#pragma unroll
        for (int i = 0; i < 16; i++) s = fmaf(yreg[i], w[lane + i * 32], s);
#pragma unroll
        for (int o = 16; o; o >>= 1) s += __shfl_xor_sync(0xffffffffu, s, o);
        if (lane == 0) out[(long long)m * Vv + n] = s + bout[n];
    }
}

// ---------------- driver ----------------
extern "C" void kernel_launch(void* const* d_in, const int* in_sizes, int n_in,
                              void* d_out, int out_size)
{
    const int*   tokens = (const int*)  d_in[0];
    const float* emb    = (const float*)d_in[1];
    const float* pos    = (const float*)d_in[2];
    const float* ln1_g  = (const float*)d_in[3];
    const float* ln1_b  = (const float*)d_in[4];
    const float* Wq     = (const float*)d_in[5];
    const float* Wk     = (const float*)d_in[6];
    const float* Wv     = (const float*)d_in[7];
    const float* ln2_g  = (const float*)d_in[8];
    const float* ln2_b  = (const float*)d_in[9];
    const float* W1     = (const float*)d_in[10];
    const float* b1     = (const float*)d_in[11];
    const float* W2     = (const float*)d_in[12];
    const float* b2     = (const float*)d_in[13];
    const float* Wout   = (const float*)d_in[14];
    const float* bout   = (const float*)d_in[15];
    float* out = (float*)d_out;

    float *y, *h, *ao;
    __half *hh, *qkvh, *vt, *sh, *uh, *wqkv, *w1, *w2;
    cudaGetSymbolAddress((void**)&y,    g_y);
    cudaGetSymbolAddress((void**)&h,    g_h);
    cudaGetSymbolAddress((void**)&hh,   g_hh);
    cudaGetSymbolAddress((void**)&qkvh, g_qkvh);
    cudaGetSymbolAddress((void**)&vt,   g_vt);
    cudaGetSymbolAddress((void**)&sh,   g_sh);
    cudaGetSymbolAddress((void**)&ao,   g_ao);
    cudaGetSymbolAddress((void**)&uh,   g_uh);
    cudaGetSymbolAddress((void**)&wqkv, g_wqkv);
    cudaGetSymbolAddress((void**)&w1,   g_w1);
    cudaGetSymbolAddress((void**)&w2,   g_w2);

    cudaFuncSetAttribute(gemmh<EPI_H,      false, false>, cudaFuncAttributeMaxDynamicSharedMemorySize, GSMEM_B);
    cudaFuncSetAttribute(gemmh<EPI_CAUSALH,false, true >, cudaFuncAttributeMaxDynamicSharedMemorySize, GSMEM_B);
    cudaFuncSetAttribute(gemmh<EPI_F32,    true,  false>, cudaFuncAttributeMaxDynamicSharedMemorySize, GSMEM_B);
    cudaFuncSetAttribute(gemmh<EPI_HRELU,  false, false>, cudaFuncAttributeMaxDynamicSharedMemorySize, GSMEM_B);
    cudaFuncSetAttribute(gemmh<EPI_BIASRES,false, false>, cudaFuncAttributeMaxDynamicSharedMemorySize, GSMEM_B);

    const int MBT = Bb * Tt;  // 8192
    const int NMAT = Hh * Dd * Ee;      // 2.10M elements per q/k/v matrix per layer
    const int NMLP = Ll * 4 * Ee * Ee;  // 5.24M

    // pack q|k|v weights per layer into wqkv [L][12288][512], fp16
    for (int l = 0; l < Ll; l++) {
        __half* dst = wqkv + (long long)l * QKVW * Ee;
        cvtwh_kernel<<<NMAT / 1024, 256>>>(Wq + (long long)l * NMAT, dst);
        cvtwh_kernel<<<NMAT / 1024, 256>>>(Wk + (long long)l * NMAT, dst + (long long)4096 * Ee);
        cvtwh_kernel<<<NMAT / 1024, 256>>>(Wv + (long long)l * NMAT, dst + (long long)8192 * Ee);
    }
    cvtwh_kernel<<<NMLP / 1024, 256>>>(W1, w1);
    cvtwh_kernel<<<NMLP / 1024, 256>>>(W2, w2);

    embed_kernel<<<(MBT * Ee) / 256, 256>>>(tokens, emb, pos, y);

    for (int l = 0; l < Ll; l++) {
        ln_kernel<<<MBT, 256>>>(y, ln1_g + l * Ee, ln1_b + l * Ee, h, hh);

        // fused QKV projection: [8192,512] x [12288,512]^T -> qkvh [8192,12288]
        dim3 gqkv(96, 64);
        gemmh<EPI_H, false, false><<<gqkv, 256, GSMEM_B>>>(
            hh, wqkv + (long long)l * QKVW * Ee, qkvh,
            512, 512, QKVW, 512, 0, 0, 0, nullptr, nullptr);

        vtrans_kernel<<<dim3(Tt / 32, Dd / 32, Bb * Hh), dim3(32, 8)>>>(qkvh, vt);

        // S = scale * Q K^T (causal), fp16 out, per head via ZQK offsets
        dim3 gqk(16, 16, 32);
        gemmh<EPI_CAUSALH, false, true><<<gqk, 256, GSMEM_B>>>(
            qkvh, qkvh, sh, QKVW, QKVW, 2048, 512, 0, 0, (long long)TT, nullptr, nullptr);

        softmaxh_kernel<<<Bb * Hh * Tt, 256>>>(sh);

        // AO = P V (NT with transposed V), causal K-bound; fp32 out
        dim3 gav(4, 16, 32);
        gemmh<EPI_F32, true, false><<<gav, 256, GSMEM_B>>>(
            sh, vt, ao, 2048, 2048, 512, 2048,
            (long long)TT, (long long)(1 << 20), (long long)TD, nullptr, nullptr);

        headsum_kernel<<<(MBT * Ee) / 1024, 256>>>(ao, y);

        ln_kernel<<<MBT, 256>>>(y, ln2_g + l * Ee, ln2_b + l * Ee, h, hh);

        // u = relu(h2 W1^T + b1), half out
        dim3 g1(16, 64);
        gemmh<EPI_HRELU, false, false><<<g1, 256, GSMEM_B>>>(
            hh, w1 + (long long)l * 4 * Ee * Ee, uh, 512, 512, 2048, 512,
            0, 0, 0, b1 + l * 4 * Ee, nullptr);

        // y = u W2^T + b2 + h2, fp32 out
        dim3 g2(4, 64);
        gemmh<EPI_BIASRES, false, false><<<g2, 256, GSMEM_B>>>(
            uh, w2 + (long long)l * Ee * 4 * Ee, y, 2048, 2048, 512, 2048,
            0, 0, 0, b2 + l * Ee, h);
    }

    logits_kernel<<<MBT / 8, 256>>>(y, Wout, bout, out);
}